// round 14
// baseline (speedup 1.0000x reference)
#include <cuda_runtime.h>
#include <cuda_fp16.h>
#include <cstdint>

// ---------------------------------------------------------------------------
// Experts MoE, fp16 mma.sync m16n8k16, fp32 accum (compute_103-safe).
// Round 14: R13 (mbarrier-tracked cp.async pipeline, no mainloop syncs)
// with per-WARP empty-barrier arrivals (init 8, lane0 arrives) instead of
// per-thread (init 256) -> 32x less single-address mbarrier ATOMS traffic.
// 2 CTAs/SM x 256 thr, 128x128 block, 32x64 warp tiles, XOR-swizzled smem,
// 3 stages. W2 convert folded into gemm1's grid; X/W1 convert fused.
// ---------------------------------------------------------------------------

#define NEXPERTS 8
#define TOK_E    2048
#define HID      2048
#define FFN      1408
#define FFN2     2816

#define TILE_B 16384
#define STG    (2 * TILE_B)             // 32768
#define MBAR_OFF (3 * STG)              // 6 x 8B barriers after tiles
#define SMEM_TOTAL (3 * STG + 64)       // 98368 -> 2 CTAs/SM

#define W2_F4_PER_CTA 90112             // (8*1408*2048/4)/64

__device__ __half g_Xh [(size_t)TOK_E * NEXPERTS * HID];
__device__ __half g_W1h[(size_t)NEXPERTS * HID * FFN2];    // [e][k][n] fp16
__device__ __half g_W2h[(size_t)NEXPERTS * FFN * HID];     // [e][k][n] fp16
__device__ __half g_act[(size_t)NEXPERTS * TOK_E * FFN];

__device__ __forceinline__ uint32_t s2u(const void* p) {
    uint32_t a;
    asm("{ .reg .u64 t; cvta.to.shared.u64 t, %1; cvt.u32.u64 %0, t; }" : "=r"(a) : "l"(p));
    return a;
}
__device__ __forceinline__ void cpa16(uint32_t s, const void* g) {
    asm volatile("cp.async.cg.shared.global [%0], [%1], 16;" :: "r"(s), "l"(g));
}
__device__ __forceinline__ void mbar_init(uint32_t a, uint32_t n) {
    asm volatile("mbarrier.init.shared.b64 [%0], %1;" :: "r"(a), "r"(n) : "memory");
}
__device__ __forceinline__ void cpa_arrive(uint32_t a) {
    asm volatile("cp.async.mbarrier.arrive.noinc.shared.b64 [%0];" :: "r"(a) : "memory");
}
__device__ __forceinline__ void mbar_arrive(uint32_t a) {
    asm volatile("mbarrier.arrive.shared.b64 _, [%0];" :: "r"(a) : "memory");
}
__device__ __forceinline__ void mbar_wait(uint32_t a, uint32_t ph) {
    uint32_t done;
    asm volatile(
        "{ .reg .pred p; mbarrier.try_wait.parity.acquire.cta.shared::cta.b64 p, [%1], %2; selp.b32 %0,1,0,p; }"
        : "=r"(done) : "r"(a), "r"(ph) : "memory");
    if (!done) {
        asm volatile(
            "{ .reg .pred P1;\nW_%=:\n mbarrier.try_wait.parity.acquire.cta.shared::cta.b64 P1, [%0], %1, 0x989680;\n @P1 bra.uni D_%=;\n bra.uni W_%=;\nD_%=:\n}"
            :: "r"(a), "r"(ph) : "memory");
    }
}
__device__ __forceinline__ void ldsm4(uint32_t* r, uint32_t addr) {
    asm volatile("ldmatrix.sync.aligned.m8n8.x4.shared.b16 {%0,%1,%2,%3}, [%4];"
                 : "=r"(r[0]), "=r"(r[1]), "=r"(r[2]), "=r"(r[3]) : "r"(addr));
}
__device__ __forceinline__ void ldsm4t(uint32_t* r, uint32_t addr) {
    asm volatile("ldmatrix.sync.aligned.m8n8.x4.trans.shared.b16 {%0,%1,%2,%3}, [%4];"
                 : "=r"(r[0]), "=r"(r[1]), "=r"(r[2]), "=r"(r[3]) : "r"(addr));
}
__device__ __forceinline__ void mma16(float d[4], const uint32_t a[4], uint32_t b0, uint32_t b1) {
    asm volatile(
        "mma.sync.aligned.m16n8k16.row.col.f32.f16.f16.f32 "
        "{%0,%1,%2,%3}, {%4,%5,%6,%7}, {%8,%9}, {%0,%1,%2,%3};\n"
        : "+f"(d[0]), "+f"(d[1]), "+f"(d[2]), "+f"(d[3])
        : "r"(a[0]), "r"(a[1]), "r"(a[2]), "r"(a[3]), "r"(b0), "r"(b1));
}
__device__ __forceinline__ float silu(float x) { return x / (1.0f + __expf(-x)); }

__device__ __forceinline__ uint2 cvt4h(float4 v) {
    __half2 h0 = __floats2half2_rn(v.x, v.y);
    __half2 h1 = __floats2half2_rn(v.z, v.w);
    uint2 u;
    u.x = *reinterpret_cast<uint32_t*>(&h0);
    u.y = *reinterpret_cast<uint32_t*>(&h1);
    return u;
}

// ===========================================================================
// Fused streaming f32 -> fp16 convert for X and W1 (one launch)
// ===========================================================================
__global__ __launch_bounds__(256)
void cvt_fused_kernel(const float* __restrict__ X, const float* __restrict__ W1,
                      __half* __restrict__ xh, __half* __restrict__ w1h,
                      size_t nX4, size_t nTot4) {
    for (size_t i = (size_t)blockIdx.x * blockDim.x + threadIdx.x; i < nTot4;
         i += (size_t)gridDim.x * blockDim.x) {
        if (i < nX4) {
            reinterpret_cast<uint2*>(xh)[i] =
                cvt4h(reinterpret_cast<const float4*>(X)[i]);
        } else {
            const size_t j = i - nX4;
            reinterpret_cast<uint2*>(w1h)[j] =
                cvt4h(reinterpret_cast<const float4*>(W1)[j]);
        }
    }
}

// ===========================================================================
// Pipelined compute for one BK=64 stage (A hoisted, B ping-pong).
// ===========================================================================
#define COMPUTE_STAGE(sa, sB)                                                   \
    {                                                                           \
        uint32_t afr[4][2][4];                                                  \
        _Pragma("unroll")                                                       \
        for (int ks = 0; ks < 4; ks++)                                          \
            _Pragma("unroll")                                                   \
            for (int mt = 0; mt < 2; mt++)                                      \
                ldsm4(afr[ks][mt],                                              \
                      (sa) + aRow[mt] + ((((uint32_t)(2 * ks) + hiA) ^ aS[mt]) << 4)); \
        uint32_t bf[2][4];                                                      \
        ldsm4t(bf[0], (sB) + rowB + swB[0]);                                    \
        _Pragma("unroll")                                                       \
        for (int s = 0; s < 16; s++) {                                          \
            const int ks = s >> 2, nq = s & 3;                                  \
            const int cur = s & 1, nxt = cur ^ 1;                               \
            if (s < 15) {                                                       \
                const int s1 = s + 1;                                           \
                ldsm4t(bf[nxt], (sB) + (uint32_t)((s1 >> 2) * 4096) + rowB + swB[s1 & 3]); \
            }                                                                   \
            mma16(acc[0][nq * 2 + 0], afr[ks][0], bf[cur][0], bf[cur][1]);      \
            mma16(acc[1][nq * 2 + 0], afr[ks][1], bf[cur][0], bf[cur][1]);      \
            mma16(acc[0][nq * 2 + 1], afr[ks][0], bf[cur][2], bf[cur][3]);      \
            mma16(acc[1][nq * 2 + 1], afr[ks][1], bf[cur][2], bf[cur][3]);      \
        }                                                                       \
    }

// mbarrier pipeline: full[s] (init 256) flips when ALL threads' stage-s
// copies land; empty[s] (init 8) flips when all 8 warps' lane-0 arrive after
// consuming (ldmatrix.sync is warp-collective -> lane0 arrive after the
// warp's COMPUTE_STAGE proves all 32 lanes' smem reads retired).
#define MAIN_LOOP(NT)                                                           \
    issue(0); cpa_arrive(mbF + 0 * 8);                                          \
    issue(1); cpa_arrive(mbF + 1 * 8);                                          \
    for (int kt = 0; kt < (NT); kt++) {                                         \
        const int st = kt % 3;                                                  \
        mbar_wait(mbF + (uint32_t)st * 8, (uint32_t)((kt / 3) & 1));            \
        {                                                                       \
            const uint32_t sa = sb + (uint32_t)st * STG;                        \
            const uint32_t sB = sa + TILE_B;                                    \
            COMPUTE_STAGE(sa, sB)                                               \
        }                                                                       \
        if (lane == 0) mbar_arrive(mbE + (uint32_t)st * 8);                     \
        const int j = kt + 2;                                                   \
        if (j < (NT)) {                                                         \
            const int s2 = j % 3;                                               \
            if (j >= 3)                                                         \
                mbar_wait(mbE + (uint32_t)s2 * 8, (uint32_t)(((j / 3) + 1) & 1)); \
            issue(j);                                                           \
            cpa_arrive(mbF + (uint32_t)s2 * 8);                                 \
        }                                                                       \
    }

#define MBAR_SETUP()                                                            \
    const uint32_t mbF = sb + MBAR_OFF;                                         \
    const uint32_t mbE = sb + MBAR_OFF + 24;                                    \
    if (tid == 0) {                                                             \
        for (int s = 0; s < 3; s++) { mbar_init(mbF + s * 8, 256); mbar_init(mbE + s * 8, 8); } \
    }                                                                           \
    __syncthreads();

// ===========================================================================
// GEMM1 + swiglu. ntile 0..21 = GEMM (128m x 64 act-cols); ntile 22 = W2 cvt.
// B stage n-cols: [a(0:32) | b(0:32) | a(32:64) | b(32:64)] (k-major rows).
// ===========================================================================
__global__ __launch_bounds__(256, 2)
void gemm1_kernel(const float* __restrict__ W2src) {
    if (blockIdx.x == 22) {
        if (blockIdx.y >= 8) return;
        const size_t cid = (size_t)blockIdx.z * 8 + blockIdx.y;
        const float4* s4 = reinterpret_cast<const float4*>(W2src) + cid * W2_F4_PER_CTA;
        uint2* d4 = reinterpret_cast<uint2*>(g_W2h) + cid * W2_F4_PER_CTA;
        #pragma unroll 4
        for (int i = threadIdx.x; i < W2_F4_PER_CTA; i += 256)
            d4[i] = cvt4h(s4[i]);
        return;
    }

    const int e = blockIdx.z, mtile = blockIdx.y, ntile = blockIdx.x;
    const int tid = threadIdx.x, warp = tid >> 5, lane = tid & 31;
    const int wm = warp >> 1, wn = warp & 1;
    extern __shared__ char smem[];
    const uint32_t sb = s2u(smem);
    const int n0 = ntile * 64;

    const int pr = tid >> 3, kc = tid & 7;
    const uint32_t swcA = (uint32_t)((kc ^ (pr & 7)) << 4);
    uint32_t dOffA[4];
    const __half* aSrc[4];
    {
        const __half* xe = g_Xh + ((size_t)(e * TOK_E + mtile * 128)) * HID + kc * 8;
        #pragma unroll
        for (int i = 0; i < 4; i++) {
            dOffA[i] = (uint32_t)((pr + 32 * i) * 128) + swcA;
            aSrc[i]  = xe + (size_t)(pr + 32 * i) * HID;
        }
    }

    const int rB = tid >> 3, cB = tid & 7;
    uint32_t dOffB[4];
    const __half* bSrc[4];
    {
        const __half* w1e = g_W1h + (size_t)e * HID * FFN2;
        #pragma unroll
        for (int j = 0; j < 4; j++) {
            const int row = rB + (j >> 1) * 32;
            const int ch  = cB + (j & 1) * 8;
            const int g   = ch >> 2;
            const int col = n0 + (g >> 1) * 32 + (ch & 3) * 8 + ((g & 1) ? FFN : 0);
            dOffB[j] = (uint32_t)(row * 256 + ((ch ^ (rB & 7)) << 4));
            bSrc[j]  = w1e + (size_t)row * FFN2 + col;
        }
    }

    const uint32_t hiA = lane >> 4;
    uint32_t aRow[2], aS[2];
    #pragma unroll
    for (int mt = 0; mt < 2; mt++) {
        const int r = wm * 32 + mt * 16 + (lane & 15);
        aRow[mt] = (uint32_t)(r * 128); aS[mt] = (uint32_t)(r & 7);
    }
    const uint32_t rowB = (uint32_t)((((lane >> 3) & 1) * 8 + (lane & 7)) * 256);
    uint32_t swB[4];
    #pragma unroll
    for (int nq = 0; nq < 4; nq++)
        swB[nq] = (uint32_t)((((wn * 8 + nq * 2 + (lane >> 4)) ^ (lane & 7))) << 4);

    float acc[2][8][4] = {};

    MBAR_SETUP()

    auto issue = [&](int kt) {
        const uint32_t s  = sb + (uint32_t)(kt % 3) * STG;
        const uint32_t sB = s + TILE_B;
        #pragma unroll
        for (int i = 0; i < 4; i++) cpa16(s  + dOffA[i], aSrc[i] + (size_t)kt * 64);
        #pragma unroll
        for (int j = 0; j < 4; j++) cpa16(sB + dOffB[j], bSrc[j] + (size_t)kt * (64 * FFN2));
    };

    MAIN_LOOP(32)

    const int lg = lane >> 2, lt = lane & 3;
    __half* actBase = g_act + ((size_t)(e * TOK_E + mtile * 128)) * FFN + n0 + wn * 32;
    #pragma unroll
    for (int mt = 0; mt < 2; mt++) {
        #pragma unroll
        for (int j = 0; j < 4; j++) {
            const int r = wm * 32 + mt * 16 + lg;
            const int c = 8 * j + 2 * lt;
            const float* pa = acc[mt][j];
            const float* pb = acc[mt][4 + j];
            __half2 v0 = __floats2half2_rn(silu(pa[0]) * pb[0], silu(pa[1]) * pb[1]);
            __half2 v1 = __floats2half2_rn(silu(pa[2]) * pb[2], silu(pa[3]) * pb[3]);
            *reinterpret_cast<__half2*>(actBase + (size_t)r * FFN + c)       = v0;
            *reinterpret_cast<__half2*>(actBase + (size_t)(r + 8) * FFN + c) = v1;
        }
    }
}

// ===========================================================================
// GEMM2: block 128m x 128n
// ===========================================================================
__global__ __launch_bounds__(256, 2)
void gemm2_kernel(float* __restrict__ out) {
    const int e = blockIdx.z, mtile = blockIdx.y, ntile = blockIdx.x;
    const int tid = threadIdx.x, warp = tid >> 5, lane = tid & 31;
    const int wm = warp >> 1, wn = warp & 1;
    extern __shared__ char smem[];
    const uint32_t sb = s2u(smem);
    const int n0 = ntile * 128;

    const int pr = tid >> 3, kc = tid & 7;
    const uint32_t swcA = (uint32_t)((kc ^ (pr & 7)) << 4);
    uint32_t dOffA[4];
    const __half* aSrc[4];
    {
        const __half* ae = g_act + ((size_t)(e * TOK_E + mtile * 128)) * FFN + kc * 8;
        #pragma unroll
        for (int i = 0; i < 4; i++) {
            dOffA[i] = (uint32_t)((pr + 32 * i) * 128) + swcA;
            aSrc[i]  = ae + (size_t)(pr + 32 * i) * FFN;
        }
    }

    const int rB = tid >> 3, cB = tid & 7;
    uint32_t dOffB[4];
    const __half* bSrc[4];
    {
        const __half* w2e = g_W2h + (size_t)e * FFN * HID;
        #pragma unroll
        for (int j = 0; j < 4; j++) {
            const int row = rB + (j >> 1) * 32;
            const int ch  = cB + (j & 1) * 8;
            dOffB[j] = (uint32_t)(row * 256 + ((ch ^ (rB & 7)) << 4));
            bSrc[j]  = w2e + (size_t)row * HID + n0 + ch * 8;
        }
    }

    const uint32_t hiA = lane >> 4;
    uint32_t aRow[2], aS[2];
    #pragma unroll
    for (int mt = 0; mt < 2; mt++) {
        const int r = wm * 32 + mt * 16 + (lane & 15);
        aRow[mt] = (uint32_t)(r * 128); aS[mt] = (uint32_t)(r & 7);
    }
    const uint32_t rowB = (uint32_t)((((lane >> 3) & 1) * 8 + (lane & 7)) * 256);
    uint32_t swB[4];
    #pragma unroll
    for (int nq = 0; nq < 4; nq++)
        swB[nq] = (uint32_t)((((wn * 8 + nq * 2 + (lane >> 4)) ^ (lane & 7))) << 4);

    float acc[2][8][4] = {};

    MBAR_SETUP()

    auto issue = [&](int kt) {
        const uint32_t s  = sb + (uint32_t)(kt % 3) * STG;
        const uint32_t sB = s + TILE_B;
        #pragma unroll
        for (int i = 0; i < 4; i++) cpa16(s  + dOffA[i], aSrc[i] + (size_t)kt * 64);
        #pragma unroll
        for (int j = 0; j < 4; j++) cpa16(sB + dOffB[j], bSrc[j] + (size_t)kt * (64 * HID));
    };

    MAIN_LOOP(22)

    const int lg = lane >> 2, lt = lane & 3;
    float* outBase = out + ((size_t)(e * TOK_E + mtile * 128)) * HID + n0 + wn * 64;
    #pragma unroll
    for (int mt = 0; mt < 2; mt++) {
        #pragma unroll
        for (int j = 0; j < 8; j++) {
            const int r = wm * 32 + mt * 16 + lg;
            const int c = 8 * j + 2 * lt;
            const float* d = acc[mt][j];
            *reinterpret_cast<float2*>(outBase + (size_t)r * HID + c)       = make_float2(d[0], d[1]);
            *reinterpret_cast<float2*>(outBase + (size_t)(r + 8) * HID + c) = make_float2(d[2], d[3]);
        }
    }
}

// ===========================================================================
// Launch
// ===========================================================================
extern "C" void kernel_launch(void* const* d_in, const int* in_sizes, int n_in,
                              void* d_out, int out_size) {
    const float* X  = (const float*)d_in[0];
    const float* W1 = (const float*)d_in[2];
    const float* W2 = (const float*)d_in[3];
    float* out = (float*)d_out;

    __half* xh;  cudaGetSymbolAddress((void**)&xh,  g_Xh);
    __half* w1h; cudaGetSymbolAddress((void**)&w1h, g_W1h);

    cudaFuncSetAttribute(gemm1_kernel, cudaFuncAttributeMaxDynamicSharedMemorySize, SMEM_TOTAL);
    cudaFuncSetAttribute(gemm2_kernel, cudaFuncAttributeMaxDynamicSharedMemorySize, SMEM_TOTAL);

    const size_t nX4 = (size_t)TOK_E * NEXPERTS * HID / 4;
    const size_t nW4 = (size_t)NEXPERTS * HID * FFN2 / 4;
    cvt_fused_kernel<<<4096, 256>>>(X, W1, xh, w1h, nX4, nX4 + nW4);

    gemm1_kernel<<<dim3(23, TOK_E / 128, NEXPERTS), 256, SMEM_TOTAL>>>(W2);
    gemm2_kernel<<<dim3(HID / 128, TOK_E / 128, NEXPERTS), 256, SMEM_TOTAL>>>(out);
}

// round 15
// speedup vs baseline: 1.0085x; 1.0085x over previous
#include <cuda_runtime.h>
#include <cuda_fp16.h>
#include <cstdint>

// ---------------------------------------------------------------------------
// Experts MoE, fp16 mma.sync m16n8k16, fp32 accum (compute_103-safe).
// Round 15: R13 exactly (best: 692.8us) — mbarrier-tracked cp.async pipeline
// (full init 256 / empty init 256, per-thread arrivals), no mainloop syncs,
// 2 CTAs/SM x 256 thr, 128x128 block, 32x64 warp tiles, XOR-swizzled smem,
// 3 stages — plus: all 128 embedded W2-cvt CTAs now do work (was 64+64 idle).
// ---------------------------------------------------------------------------

#define NEXPERTS 8
#define TOK_E    2048
#define HID      2048
#define FFN      1408
#define FFN2     2816

#define TILE_B 16384
#define STG    (2 * TILE_B)             // 32768
#define MBAR_OFF (3 * STG)              // 6 x 8B barriers after tiles
#define SMEM_TOTAL (3 * STG + 64)       // 98368 -> 2 CTAs/SM

#define W2_F4_PER_CTA 45056             // (8*1408*2048/4)/128

__device__ __half g_Xh [(size_t)TOK_E * NEXPERTS * HID];
__device__ __half g_W1h[(size_t)NEXPERTS * HID * FFN2];    // [e][k][n] fp16
__device__ __half g_W2h[(size_t)NEXPERTS * FFN * HID];     // [e][k][n] fp16
__device__ __half g_act[(size_t)NEXPERTS * TOK_E * FFN];

__device__ __forceinline__ uint32_t s2u(const void* p) {
    uint32_t a;
    asm("{ .reg .u64 t; cvta.to.shared.u64 t, %1; cvt.u32.u64 %0, t; }" : "=r"(a) : "l"(p));
    return a;
}
__device__ __forceinline__ void cpa16(uint32_t s, const void* g) {
    asm volatile("cp.async.cg.shared.global [%0], [%1], 16;" :: "r"(s), "l"(g));
}
__device__ __forceinline__ void mbar_init(uint32_t a, uint32_t n) {
    asm volatile("mbarrier.init.shared.b64 [%0], %1;" :: "r"(a), "r"(n) : "memory");
}
__device__ __forceinline__ void cpa_arrive(uint32_t a) {
    asm volatile("cp.async.mbarrier.arrive.noinc.shared.b64 [%0];" :: "r"(a) : "memory");
}
__device__ __forceinline__ void mbar_arrive(uint32_t a) {
    asm volatile("mbarrier.arrive.shared.b64 _, [%0];" :: "r"(a) : "memory");
}
__device__ __forceinline__ void mbar_wait(uint32_t a, uint32_t ph) {
    uint32_t done;
    asm volatile(
        "{ .reg .pred p; mbarrier.try_wait.parity.acquire.cta.shared::cta.b64 p, [%1], %2; selp.b32 %0,1,0,p; }"
        : "=r"(done) : "r"(a), "r"(ph) : "memory");
    if (!done) {
        asm volatile(
            "{ .reg .pred P1;\nW_%=:\n mbarrier.try_wait.parity.acquire.cta.shared::cta.b64 P1, [%0], %1, 0x989680;\n @P1 bra.uni D_%=;\n bra.uni W_%=;\nD_%=:\n}"
            :: "r"(a), "r"(ph) : "memory");
    }
}
__device__ __forceinline__ void ldsm4(uint32_t* r, uint32_t addr) {
    asm volatile("ldmatrix.sync.aligned.m8n8.x4.shared.b16 {%0,%1,%2,%3}, [%4];"
                 : "=r"(r[0]), "=r"(r[1]), "=r"(r[2]), "=r"(r[3]) : "r"(addr));
}
__device__ __forceinline__ void ldsm4t(uint32_t* r, uint32_t addr) {
    asm volatile("ldmatrix.sync.aligned.m8n8.x4.trans.shared.b16 {%0,%1,%2,%3}, [%4];"
                 : "=r"(r[0]), "=r"(r[1]), "=r"(r[2]), "=r"(r[3]) : "r"(addr));
}
__device__ __forceinline__ void mma16(float d[4], const uint32_t a[4], uint32_t b0, uint32_t b1) {
    asm volatile(
        "mma.sync.aligned.m16n8k16.row.col.f32.f16.f16.f32 "
        "{%0,%1,%2,%3}, {%4,%5,%6,%7}, {%8,%9}, {%0,%1,%2,%3};\n"
        : "+f"(d[0]), "+f"(d[1]), "+f"(d[2]), "+f"(d[3])
        : "r"(a[0]), "r"(a[1]), "r"(a[2]), "r"(a[3]), "r"(b0), "r"(b1));
}
__device__ __forceinline__ float silu(float x) { return x / (1.0f + __expf(-x)); }

__device__ __forceinline__ uint2 cvt4h(float4 v) {
    __half2 h0 = __floats2half2_rn(v.x, v.y);
    __half2 h1 = __floats2half2_rn(v.z, v.w);
    uint2 u;
    u.x = *reinterpret_cast<uint32_t*>(&h0);
    u.y = *reinterpret_cast<uint32_t*>(&h1);
    return u;
}

// ===========================================================================
// Fused streaming f32 -> fp16 convert for X and W1 (one launch)
// ===========================================================================
__global__ __launch_bounds__(256)
void cvt_fused_kernel(const float* __restrict__ X, const float* __restrict__ W1,
                      __half* __restrict__ xh, __half* __restrict__ w1h,
                      size_t nX4, size_t nTot4) {
    for (size_t i = (size_t)blockIdx.x * blockDim.x + threadIdx.x; i < nTot4;
         i += (size_t)gridDim.x * blockDim.x) {
        if (i < nX4) {
            reinterpret_cast<uint2*>(xh)[i] =
                cvt4h(reinterpret_cast<const float4*>(X)[i]);
        } else {
            const size_t j = i - nX4;
            reinterpret_cast<uint2*>(w1h)[j] =
                cvt4h(reinterpret_cast<const float4*>(W1)[j]);
        }
    }
}

// ===========================================================================
// Pipelined compute for one BK=64 stage (A hoisted, B ping-pong).
// ===========================================================================
#define COMPUTE_STAGE(sa, sB)                                                   \
    {                                                                           \
        uint32_t afr[4][2][4];                                                  \
        _Pragma("unroll")                                                       \
        for (int ks = 0; ks < 4; ks++)                                          \
            _Pragma("unroll")                                                   \
            for (int mt = 0; mt < 2; mt++)                                      \
                ldsm4(afr[ks][mt],                                              \
                      (sa) + aRow[mt] + ((((uint32_t)(2 * ks) + hiA) ^ aS[mt]) << 4)); \
        uint32_t bf[2][4];                                                      \
        ldsm4t(bf[0], (sB) + rowB + swB[0]);                                    \
        _Pragma("unroll")                                                       \
        for (int s = 0; s < 16; s++) {                                          \
            const int ks = s >> 2, nq = s & 3;                                  \
            const int cur = s & 1, nxt = cur ^ 1;                               \
            if (s < 15) {                                                       \
                const int s1 = s + 1;                                           \
                ldsm4t(bf[nxt], (sB) + (uint32_t)((s1 >> 2) * 4096) + rowB + swB[s1 & 3]); \
            }                                                                   \
            mma16(acc[0][nq * 2 + 0], afr[ks][0], bf[cur][0], bf[cur][1]);      \
            mma16(acc[1][nq * 2 + 0], afr[ks][1], bf[cur][0], bf[cur][1]);      \
            mma16(acc[0][nq * 2 + 1], afr[ks][0], bf[cur][2], bf[cur][3]);      \
            mma16(acc[1][nq * 2 + 1], afr[ks][1], bf[cur][2], bf[cur][3]);      \
        }                                                                       \
    }

// mbarrier pipeline mainloop (R13, proven): full[s] (init 256) flips when ALL
// threads' stage-s copies land; empty[s] (init 256) flips when all 256
// threads arrived after consuming. No __syncthreads -> warps drift 1 iter.
#define MAIN_LOOP(NT)                                                           \
    issue(0); cpa_arrive(mbF + 0 * 8);                                          \
    issue(1); cpa_arrive(mbF + 1 * 8);                                          \
    for (int kt = 0; kt < (NT); kt++) {                                         \
        const int st = kt % 3;                                                  \
        mbar_wait(mbF + (uint32_t)st * 8, (uint32_t)((kt / 3) & 1));            \
        {                                                                       \
            const uint32_t sa = sb + (uint32_t)st * STG;                        \
            const uint32_t sB = sa + TILE_B;                                    \
            COMPUTE_STAGE(sa, sB)                                               \
        }                                                                       \
        mbar_arrive(mbE + (uint32_t)st * 8);                                    \
        const int j = kt + 2;                                                   \
        if (j < (NT)) {                                                         \
            const int s2 = j % 3;                                               \
            if (j >= 3)                                                         \
                mbar_wait(mbE + (uint32_t)s2 * 8, (uint32_t)(((j / 3) + 1) & 1)); \
            issue(j);                                                           \
            cpa_arrive(mbF + (uint32_t)s2 * 8);                                 \
        }                                                                       \
    }

#define MBAR_SETUP()                                                            \
    const uint32_t mbF = sb + MBAR_OFF;                                         \
    const uint32_t mbE = sb + MBAR_OFF + 24;                                    \
    if (tid == 0) {                                                             \
        for (int s = 0; s < 3; s++) { mbar_init(mbF + s * 8, 256); mbar_init(mbE + s * 8, 256); } \
    }                                                                           \
    __syncthreads();

// ===========================================================================
// GEMM1 + swiglu. ntile 0..21 = GEMM (128m x 64 act-cols); ntile 22 = W2 cvt
// (all 128 CTAs at x=22 do work now).
// B stage n-cols: [a(0:32) | b(0:32) | a(32:64) | b(32:64)] (k-major rows).
// ===========================================================================
__global__ __launch_bounds__(256, 2)
void gemm1_kernel(const float* __restrict__ W2src) {
    if (blockIdx.x == 22) {
        const size_t cid = (size_t)blockIdx.z * 16 + blockIdx.y;   // 0..127
        const float4* s4 = reinterpret_cast<const float4*>(W2src) + cid * W2_F4_PER_CTA;
        uint2* d4 = reinterpret_cast<uint2*>(g_W2h) + cid * W2_F4_PER_CTA;
        #pragma unroll 4
        for (int i = threadIdx.x; i < W2_F4_PER_CTA; i += 256)
            d4[i] = cvt4h(s4[i]);
        return;
    }

    const int e = blockIdx.z, mtile = blockIdx.y, ntile = blockIdx.x;
    const int tid = threadIdx.x, warp = tid >> 5, lane = tid & 31;
    const int wm = warp >> 1, wn = warp & 1;
    extern __shared__ char smem[];
    const uint32_t sb = s2u(smem);
    const int n0 = ntile * 64;

    const int pr = tid >> 3, kc = tid & 7;
    const uint32_t swcA = (uint32_t)((kc ^ (pr & 7)) << 4);
    uint32_t dOffA[4];
    const __half* aSrc[4];
    {
        const __half* xe = g_Xh + ((size_t)(e * TOK_E + mtile * 128)) * HID + kc * 8;
        #pragma unroll
        for (int i = 0; i < 4; i++) {
            dOffA[i] = (uint32_t)((pr + 32 * i) * 128) + swcA;
            aSrc[i]  = xe + (size_t)(pr + 32 * i) * HID;
        }
    }

    const int rB = tid >> 3, cB = tid & 7;
    uint32_t dOffB[4];
    const __half* bSrc[4];
    {
        const __half* w1e = g_W1h + (size_t)e * HID * FFN2;
        #pragma unroll
        for (int j = 0; j < 4; j++) {
            const int row = rB + (j >> 1) * 32;
            const int ch  = cB + (j & 1) * 8;
            const int g   = ch >> 2;
            const int col = n0 + (g >> 1) * 32 + (ch & 3) * 8 + ((g & 1) ? FFN : 0);
            dOffB[j] = (uint32_t)(row * 256 + ((ch ^ (rB & 7)) << 4));
            bSrc[j]  = w1e + (size_t)row * FFN2 + col;
        }
    }

    const uint32_t hiA = lane >> 4;
    uint32_t aRow[2], aS[2];
    #pragma unroll
    for (int mt = 0; mt < 2; mt++) {
        const int r = wm * 32 + mt * 16 + (lane & 15);
        aRow[mt] = (uint32_t)(r * 128); aS[mt] = (uint32_t)(r & 7);
    }
    const uint32_t rowB = (uint32_t)((((lane >> 3) & 1) * 8 + (lane & 7)) * 256);
    uint32_t swB[4];
    #pragma unroll
    for (int nq = 0; nq < 4; nq++)
        swB[nq] = (uint32_t)((((wn * 8 + nq * 2 + (lane >> 4)) ^ (lane & 7))) << 4);

    float acc[2][8][4] = {};

    MBAR_SETUP()

    auto issue = [&](int kt) {
        const uint32_t s  = sb + (uint32_t)(kt % 3) * STG;
        const uint32_t sB = s + TILE_B;
        #pragma unroll
        for (int i = 0; i < 4; i++) cpa16(s  + dOffA[i], aSrc[i] + (size_t)kt * 64);
        #pragma unroll
        for (int j = 0; j < 4; j++) cpa16(sB + dOffB[j], bSrc[j] + (size_t)kt * (64 * FFN2));
    };

    MAIN_LOOP(32)

    const int lg = lane >> 2, lt = lane & 3;
    __half* actBase = g_act + ((size_t)(e * TOK_E + mtile * 128)) * FFN + n0 + wn * 32;
    #pragma unroll
    for (int mt = 0; mt < 2; mt++) {
        #pragma unroll
        for (int j = 0; j < 4; j++) {
            const int r = wm * 32 + mt * 16 + lg;
            const int c = 8 * j + 2 * lt;
            const float* pa = acc[mt][j];
            const float* pb = acc[mt][4 + j];
            __half2 v0 = __floats2half2_rn(silu(pa[0]) * pb[0], silu(pa[1]) * pb[1]);
            __half2 v1 = __floats2half2_rn(silu(pa[2]) * pb[2], silu(pa[3]) * pb[3]);
            *reinterpret_cast<__half2*>(actBase + (size_t)r * FFN + c)       = v0;
            *reinterpret_cast<__half2*>(actBase + (size_t)(r + 8) * FFN + c) = v1;
        }
    }
}

// ===========================================================================
// GEMM2: block 128m x 128n
// ===========================================================================
__global__ __launch_bounds__(256, 2)
void gemm2_kernel(float* __restrict__ out) {
    const int e = blockIdx.z, mtile = blockIdx.y, ntile = blockIdx.x;
    const int tid = threadIdx.x, warp = tid >> 5, lane = tid & 31;
    const int wm = warp >> 1, wn = warp & 1;
    extern __shared__ char smem[];
    const uint32_t sb = s2u(smem);
    const int n0 = ntile * 128;

    const int pr = tid >> 3, kc = tid & 7;
    const uint32_t swcA = (uint32_t)((kc ^ (pr & 7)) << 4);
    uint32_t dOffA[4];
    const __half* aSrc[4];
    {
        const __half* ae = g_act + ((size_t)(e * TOK_E + mtile * 128)) * FFN + kc * 8;
        #pragma unroll
        for (int i = 0; i < 4; i++) {
            dOffA[i] = (uint32_t)((pr + 32 * i) * 128) + swcA;
            aSrc[i]  = ae + (size_t)(pr + 32 * i) * FFN;
        }
    }

    const int rB = tid >> 3, cB = tid & 7;
    uint32_t dOffB[4];
    const __half* bSrc[4];
    {
        const __half* w2e = g_W2h + (size_t)e * FFN * HID;
        #pragma unroll
        for (int j = 0; j < 4; j++) {
            const int row = rB + (j >> 1) * 32;
            const int ch  = cB + (j & 1) * 8;
            dOffB[j] = (uint32_t)(row * 256 + ((ch ^ (rB & 7)) << 4));
            bSrc[j]  = w2e + (size_t)row * HID + n0 + ch * 8;
        }
    }

    const uint32_t hiA = lane >> 4;
    uint32_t aRow[2], aS[2];
    #pragma unroll
    for (int mt = 0; mt < 2; mt++) {
        const int r = wm * 32 + mt * 16 + (lane & 15);
        aRow[mt] = (uint32_t)(r * 128); aS[mt] = (uint32_t)(r & 7);
    }
    const uint32_t rowB = (uint32_t)((((lane >> 3) & 1) * 8 + (lane & 7)) * 256);
    uint32_t swB[4];
    #pragma unroll
    for (int nq = 0; nq < 4; nq++)
        swB[nq] = (uint32_t)((((wn * 8 + nq * 2 + (lane >> 4)) ^ (lane & 7))) << 4);

    float acc[2][8][4] = {};

    MBAR_SETUP()

    auto issue = [&](int kt) {
        const uint32_t s  = sb + (uint32_t)(kt % 3) * STG;
        const uint32_t sB = s + TILE_B;
        #pragma unroll
        for (int i = 0; i < 4; i++) cpa16(s  + dOffA[i], aSrc[i] + (size_t)kt * 64);
        #pragma unroll
        for (int j = 0; j < 4; j++) cpa16(sB + dOffB[j], bSrc[j] + (size_t)kt * (64 * HID));
    };

    MAIN_LOOP(22)

    const int lg = lane >> 2, lt = lane & 3;
    float* outBase = out + ((size_t)(e * TOK_E + mtile * 128)) * HID + n0 + wn * 64;
    #pragma unroll
    for (int mt = 0; mt < 2; mt++) {
        #pragma unroll
        for (int j = 0; j < 8; j++) {
            const int r = wm * 32 + mt * 16 + lg;
            const int c = 8 * j + 2 * lt;
            const float* d = acc[mt][j];
            *reinterpret_cast<float2*>(outBase + (size_t)r * HID + c)       = make_float2(d[0], d[1]);
            *reinterpret_cast<float2*>(outBase + (size_t)(r + 8) * HID + c) = make_float2(d[2], d[3]);
        }
    }
}

// ===========================================================================
// Launch
// ===========================================================================
extern "C" void kernel_launch(void* const* d_in, const int* in_sizes, int n_in,
                              void* d_out, int out_size) {
    const float* X  = (const float*)d_in[0];
    const float* W1 = (const float*)d_in[2];
    const float* W2 = (const float*)d_in[3];
    float* out = (float*)d_out;

    __half* xh;  cudaGetSymbolAddress((void**)&xh,  g_Xh);
    __half* w1h; cudaGetSymbolAddress((void**)&w1h, g_W1h);

    cudaFuncSetAttribute(gemm1_kernel, cudaFuncAttributeMaxDynamicSharedMemorySize, SMEM_TOTAL);
    cudaFuncSetAttribute(gemm2_kernel, cudaFuncAttributeMaxDynamicSharedMemorySize, SMEM_TOTAL);

    const size_t nX4 = (size_t)TOK_E * NEXPERTS * HID / 4;
    const size_t nW4 = (size_t)NEXPERTS * HID * FFN2 / 4;
    cvt_fused_kernel<<<4096, 256>>>(X, W1, xh, w1h, nX4, nX4 + nW4);

    gemm1_kernel<<<dim3(23, TOK_E / 128, NEXPERTS), 256, SMEM_TOTAL>>>(W2);
    gemm2_kernel<<<dim3(HID / 128, TOK_E / 128, NEXPERTS), 256, SMEM_TOTAL>>>(out);
}

// round 16
// speedup vs baseline: 1.0172x; 1.0086x over previous
#include <cuda_runtime.h>
#include <cuda_fp16.h>
#include <cstdint>

// ---------------------------------------------------------------------------
// Experts MoE, fp16 mma.sync m16n8k16, fp32 accum (compute_103-safe).
// Round 16: exact restore of the measured optimum (R13, 692.8us).
// - mbarrier-tracked cp.async pipeline (full/empty per stage, both init 256,
//   per-thread arrivals) -> NO __syncthreads in the mainloop; warps drift.
// - 2 CTAs/SM x 256 thr, 128x128 block, 32x64 warp tiles, XOR-swizzled smem,
//   3 stages, BK=64.
// - W2 convert folded into gemm1's grid (64 working CTAs at x=22).
// - X/W1 convert fused into one streaming kernel (DRAM-floor, 76us).
// ---------------------------------------------------------------------------

#define NEXPERTS 8
#define TOK_E    2048
#define HID      2048
#define FFN      1408
#define FFN2     2816

#define TILE_B 16384
#define STG    (2 * TILE_B)             // 32768
#define MBAR_OFF (3 * STG)              // 6 x 8B barriers after tiles
#define SMEM_TOTAL (3 * STG + 64)       // 98368 -> 2 CTAs/SM

#define W2_F4_PER_CTA 90112             // (8*1408*2048/4)/64

__device__ __half g_Xh [(size_t)TOK_E * NEXPERTS * HID];
__device__ __half g_W1h[(size_t)NEXPERTS * HID * FFN2];    // [e][k][n] fp16
__device__ __half g_W2h[(size_t)NEXPERTS * FFN * HID];     // [e][k][n] fp16
__device__ __half g_act[(size_t)NEXPERTS * TOK_E * FFN];

__device__ __forceinline__ uint32_t s2u(const void* p) {
    uint32_t a;
    asm("{ .reg .u64 t; cvta.to.shared.u64 t, %1; cvt.u32.u64 %0, t; }" : "=r"(a) : "l"(p));
    return a;
}
__device__ __forceinline__ void cpa16(uint32_t s, const void* g) {
    asm volatile("cp.async.cg.shared.global [%0], [%1], 16;" :: "r"(s), "l"(g));
}
__device__ __forceinline__ void mbar_init(uint32_t a, uint32_t n) {
    asm volatile("mbarrier.init.shared.b64 [%0], %1;" :: "r"(a), "r"(n) : "memory");
}
__device__ __forceinline__ void cpa_arrive(uint32_t a) {
    asm volatile("cp.async.mbarrier.arrive.noinc.shared.b64 [%0];" :: "r"(a) : "memory");
}
__device__ __forceinline__ void mbar_arrive(uint32_t a) {
    asm volatile("mbarrier.arrive.shared.b64 _, [%0];" :: "r"(a) : "memory");
}
__device__ __forceinline__ void mbar_wait(uint32_t a, uint32_t ph) {
    uint32_t done;
    asm volatile(
        "{ .reg .pred p; mbarrier.try_wait.parity.acquire.cta.shared::cta.b64 p, [%1], %2; selp.b32 %0,1,0,p; }"
        : "=r"(done) : "r"(a), "r"(ph) : "memory");
    if (!done) {
        asm volatile(
            "{ .reg .pred P1;\nW_%=:\n mbarrier.try_wait.parity.acquire.cta.shared::cta.b64 P1, [%0], %1, 0x989680;\n @P1 bra.uni D_%=;\n bra.uni W_%=;\nD_%=:\n}"
            :: "r"(a), "r"(ph) : "memory");
    }
}
__device__ __forceinline__ void ldsm4(uint32_t* r, uint32_t addr) {
    asm volatile("ldmatrix.sync.aligned.m8n8.x4.shared.b16 {%0,%1,%2,%3}, [%4];"
                 : "=r"(r[0]), "=r"(r[1]), "=r"(r[2]), "=r"(r[3]) : "r"(addr));
}
__device__ __forceinline__ void ldsm4t(uint32_t* r, uint32_t addr) {
    asm volatile("ldmatrix.sync.aligned.m8n8.x4.trans.shared.b16 {%0,%1,%2,%3}, [%4];"
                 : "=r"(r[0]), "=r"(r[1]), "=r"(r[2]), "=r"(r[3]) : "r"(addr));
}
__device__ __forceinline__ void mma16(float d[4], const uint32_t a[4], uint32_t b0, uint32_t b1) {
    asm volatile(
        "mma.sync.aligned.m16n8k16.row.col.f32.f16.f16.f32 "
        "{%0,%1,%2,%3}, {%4,%5,%6,%7}, {%8,%9}, {%0,%1,%2,%3};\n"
        : "+f"(d[0]), "+f"(d[1]), "+f"(d[2]), "+f"(d[3])
        : "r"(a[0]), "r"(a[1]), "r"(a[2]), "r"(a[3]), "r"(b0), "r"(b1));
}
__device__ __forceinline__ float silu(float x) { return x / (1.0f + __expf(-x)); }

__device__ __forceinline__ uint2 cvt4h(float4 v) {
    __half2 h0 = __floats2half2_rn(v.x, v.y);
    __half2 h1 = __floats2half2_rn(v.z, v.w);
    uint2 u;
    u.x = *reinterpret_cast<uint32_t*>(&h0);
    u.y = *reinterpret_cast<uint32_t*>(&h1);
    return u;
}

// ===========================================================================
// Fused streaming f32 -> fp16 convert for X and W1 (one launch)
// ===========================================================================
__global__ __launch_bounds__(256)
void cvt_fused_kernel(const float* __restrict__ X, const float* __restrict__ W1,
                      __half* __restrict__ xh, __half* __restrict__ w1h,
                      size_t nX4, size_t nTot4) {
    for (size_t i = (size_t)blockIdx.x * blockDim.x + threadIdx.x; i < nTot4;
         i += (size_t)gridDim.x * blockDim.x) {
        if (i < nX4) {
            reinterpret_cast<uint2*>(xh)[i] =
                cvt4h(reinterpret_cast<const float4*>(X)[i]);
        } else {
            const size_t j = i - nX4;
            reinterpret_cast<uint2*>(w1h)[j] =
                cvt4h(reinterpret_cast<const float4*>(W1)[j]);
        }
    }
}

// ===========================================================================
// Pipelined compute for one BK=64 stage (A hoisted, B ping-pong).
// ===========================================================================
#define COMPUTE_STAGE(sa, sB)                                                   \
    {                                                                           \
        uint32_t afr[4][2][4];                                                  \
        _Pragma("unroll")                                                       \
        for (int ks = 0; ks < 4; ks++)                                          \
            _Pragma("unroll")                                                   \
            for (int mt = 0; mt < 2; mt++)                                      \
                ldsm4(afr[ks][mt],                                              \
                      (sa) + aRow[mt] + ((((uint32_t)(2 * ks) + hiA) ^ aS[mt]) << 4)); \
        uint32_t bf[2][4];                                                      \
        ldsm4t(bf[0], (sB) + rowB + swB[0]);                                    \
        _Pragma("unroll")                                                       \
        for (int s = 0; s < 16; s++) {                                          \
            const int ks = s >> 2, nq = s & 3;                                  \
            const int cur = s & 1, nxt = cur ^ 1;                               \
            if (s < 15) {                                                       \
                const int s1 = s + 1;                                           \
                ldsm4t(bf[nxt], (sB) + (uint32_t)((s1 >> 2) * 4096) + rowB + swB[s1 & 3]); \
            }                                                                   \
            mma16(acc[0][nq * 2 + 0], afr[ks][0], bf[cur][0], bf[cur][1]);      \
            mma16(acc[1][nq * 2 + 0], afr[ks][1], bf[cur][0], bf[cur][1]);      \
            mma16(acc[0][nq * 2 + 1], afr[ks][0], bf[cur][2], bf[cur][3]);      \
            mma16(acc[1][nq * 2 + 1], afr[ks][1], bf[cur][2], bf[cur][3]);      \
        }                                                                       \
    }

// mbarrier pipeline mainloop (R13, proven): full[s] (init 256) flips when ALL
// threads' stage-s copies land; empty[s] (init 256) flips when all 256
// threads arrived after consuming. No __syncthreads -> warps drift 1 iter.
#define MAIN_LOOP(NT)                                                           \
    issue(0); cpa_arrive(mbF + 0 * 8);                                          \
    issue(1); cpa_arrive(mbF + 1 * 8);                                          \
    for (int kt = 0; kt < (NT); kt++) {                                         \
        const int st = kt % 3;                                                  \
        mbar_wait(mbF + (uint32_t)st * 8, (uint32_t)((kt / 3) & 1));            \
        {                                                                       \
            const uint32_t sa = sb + (uint32_t)st * STG;                        \
            const uint32_t sB = sa + TILE_B;                                    \
            COMPUTE_STAGE(sa, sB)                                               \
        }                                                                       \
        mbar_arrive(mbE + (uint32_t)st * 8);                                    \
        const int j = kt + 2;                                                   \
        if (j < (NT)) {                                                         \
            const int s2 = j % 3;                                               \
            if (j >= 3)                                                         \
                mbar_wait(mbE + (uint32_t)s2 * 8, (uint32_t)(((j / 3) + 1) & 1)); \
            issue(j);                                                           \
            cpa_arrive(mbF + (uint32_t)s2 * 8);                                 \
        }                                                                       \
    }

#define MBAR_SETUP()                                                            \
    const uint32_t mbF = sb + MBAR_OFF;                                         \
    const uint32_t mbE = sb + MBAR_OFF + 24;                                    \
    if (tid == 0) {                                                             \
        for (int s = 0; s < 3; s++) { mbar_init(mbF + s * 8, 256); mbar_init(mbE + s * 8, 256); } \
    }                                                                           \
    __syncthreads();

// ===========================================================================
// GEMM1 + swiglu. ntile 0..21 = GEMM (128m x 64 act-cols); ntile 22 = W2 cvt.
// B stage n-cols: [a(0:32) | b(0:32) | a(32:64) | b(32:64)] (k-major rows).
// ===========================================================================
__global__ __launch_bounds__(256, 2)
void gemm1_kernel(const float* __restrict__ W2src) {
    if (blockIdx.x == 22) {
        if (blockIdx.y >= 8) return;
        const size_t cid = (size_t)blockIdx.z * 8 + blockIdx.y;
        const float4* s4 = reinterpret_cast<const float4*>(W2src) + cid * W2_F4_PER_CTA;
        uint2* d4 = reinterpret_cast<uint2*>(g_W2h) + cid * W2_F4_PER_CTA;
        #pragma unroll 4
        for (int i = threadIdx.x; i < W2_F4_PER_CTA; i += 256)
            d4[i] = cvt4h(s4[i]);
        return;
    }

    const int e = blockIdx.z, mtile = blockIdx.y, ntile = blockIdx.x;
    const int tid = threadIdx.x, warp = tid >> 5, lane = tid & 31;
    const int wm = warp >> 1, wn = warp & 1;
    extern __shared__ char smem[];
    const uint32_t sb = s2u(smem);
    const int n0 = ntile * 64;

    const int pr = tid >> 3, kc = tid & 7;
    const uint32_t swcA = (uint32_t)((kc ^ (pr & 7)) << 4);
    uint32_t dOffA[4];
    const __half* aSrc[4];
    {
        const __half* xe = g_Xh + ((size_t)(e * TOK_E + mtile * 128)) * HID + kc * 8;
        #pragma unroll
        for (int i = 0; i < 4; i++) {
            dOffA[i] = (uint32_t)((pr + 32 * i) * 128) + swcA;
            aSrc[i]  = xe + (size_t)(pr + 32 * i) * HID;
        }
    }

    const int rB = tid >> 3, cB = tid & 7;
    uint32_t dOffB[4];
    const __half* bSrc[4];
    {
        const __half* w1e = g_W1h + (size_t)e * HID * FFN2;
        #pragma unroll
        for (int j = 0; j < 4; j++) {
            const int row = rB + (j >> 1) * 32;
            const int ch  = cB + (j & 1) * 8;
            const int g   = ch >> 2;
            const int col = n0 + (g >> 1) * 32 + (ch & 3) * 8 + ((g & 1) ? FFN : 0);
            dOffB[j] = (uint32_t)(row * 256 + ((ch ^ (rB & 7)) << 4));
            bSrc[j]  = w1e + (size_t)row * FFN2 + col;
        }
    }

    const uint32_t hiA = lane >> 4;
    uint32_t aRow[2], aS[2];
    #pragma unroll
    for (int mt = 0; mt < 2; mt++) {
        const int r = wm * 32 + mt * 16 + (lane & 15);
        aRow[mt] = (uint32_t)(r * 128); aS[mt] = (uint32_t)(r & 7);
    }
    const uint32_t rowB = (uint32_t)((((lane >> 3) & 1) * 8 + (lane & 7)) * 256);
    uint32_t swB[4];
    #pragma unroll
    for (int nq = 0; nq < 4; nq++)
        swB[nq] = (uint32_t)((((wn * 8 + nq * 2 + (lane >> 4)) ^ (lane & 7))) << 4);

    float acc[2][8][4] = {};

    MBAR_SETUP()

    auto issue = [&](int kt) {
        const uint32_t s  = sb + (uint32_t)(kt % 3) * STG;
        const uint32_t sB = s + TILE_B;
        #pragma unroll
        for (int i = 0; i < 4; i++) cpa16(s  + dOffA[i], aSrc[i] + (size_t)kt * 64);
        #pragma unroll
        for (int j = 0; j < 4; j++) cpa16(sB + dOffB[j], bSrc[j] + (size_t)kt * (64 * FFN2));
    };

    MAIN_LOOP(32)

    const int lg = lane >> 2, lt = lane & 3;
    __half* actBase = g_act + ((size_t)(e * TOK_E + mtile * 128)) * FFN + n0 + wn * 32;
    #pragma unroll
    for (int mt = 0; mt < 2; mt++) {
        #pragma unroll
        for (int j = 0; j < 4; j++) {
            const int r = wm * 32 + mt * 16 + lg;
            const int c = 8 * j + 2 * lt;
            const float* pa = acc[mt][j];
            const float* pb = acc[mt][4 + j];
            __half2 v0 = __floats2half2_rn(silu(pa[0]) * pb[0], silu(pa[1]) * pb[1]);
            __half2 v1 = __floats2half2_rn(silu(pa[2]) * pb[2], silu(pa[3]) * pb[3]);
            *reinterpret_cast<__half2*>(actBase + (size_t)r * FFN + c)       = v0;
            *reinterpret_cast<__half2*>(actBase + (size_t)(r + 8) * FFN + c) = v1;
        }
    }
}

// ===========================================================================
// GEMM2: block 128m x 128n
// ===========================================================================
__global__ __launch_bounds__(256, 2)
void gemm2_kernel(float* __restrict__ out) {
    const int e = blockIdx.z, mtile = blockIdx.y, ntile = blockIdx.x;
    const int tid = threadIdx.x, warp = tid >> 5, lane = tid & 31;
    const int wm = warp >> 1, wn = warp & 1;
    extern __shared__ char smem[];
    const uint32_t sb = s2u(smem);
    const int n0 = ntile * 128;

    const int pr = tid >> 3, kc = tid & 7;
    const uint32_t swcA = (uint32_t)((kc ^ (pr & 7)) << 4);
    uint32_t dOffA[4];
    const __half* aSrc[4];
    {
        const __half* ae = g_act + ((size_t)(e * TOK_E + mtile * 128)) * FFN + kc * 8;
        #pragma unroll
        for (int i = 0; i < 4; i++) {
            dOffA[i] = (uint32_t)((pr + 32 * i) * 128) + swcA;
            aSrc[i]  = ae + (size_t)(pr + 32 * i) * FFN;
        }
    }

    const int rB = tid >> 3, cB = tid & 7;
    uint32_t dOffB[4];
    const __half* bSrc[4];
    {
        const __half* w2e = g_W2h + (size_t)e * FFN * HID;
        #pragma unroll
        for (int j = 0; j < 4; j++) {
            const int row = rB + (j >> 1) * 32;
            const int ch  = cB + (j & 1) * 8;
            dOffB[j] = (uint32_t)(row * 256 + ((ch ^ (rB & 7)) << 4));
            bSrc[j]  = w2e + (size_t)row * HID + n0 + ch * 8;
        }
    }

    const uint32_t hiA = lane >> 4;
    uint32_t aRow[2], aS[2];
    #pragma unroll
    for (int mt = 0; mt < 2; mt++) {
        const int r = wm * 32 + mt * 16 + (lane & 15);
        aRow[mt] = (uint32_t)(r * 128); aS[mt] = (uint32_t)(r & 7);
    }
    const uint32_t rowB = (uint32_t)((((lane >> 3) & 1) * 8 + (lane & 7)) * 256);
    uint32_t swB[4];
    #pragma unroll
    for (int nq = 0; nq < 4; nq++)
        swB[nq] = (uint32_t)((((wn * 8 + nq * 2 + (lane >> 4)) ^ (lane & 7))) << 4);

    float acc[2][8][4] = {};

    MBAR_SETUP()

    auto issue = [&](int kt) {
        const uint32_t s  = sb + (uint32_t)(kt % 3) * STG;
        const uint32_t sB = s + TILE_B;
        #pragma unroll
        for (int i = 0; i < 4; i++) cpa16(s  + dOffA[i], aSrc[i] + (size_t)kt * 64);
        #pragma unroll
        for (int j = 0; j < 4; j++) cpa16(sB + dOffB[j], bSrc[j] + (size_t)kt * (64 * HID));
    };

    MAIN_LOOP(22)

    const int lg = lane >> 2, lt = lane & 3;
    float* outBase = out + ((size_t)(e * TOK_E + mtile * 128)) * HID + n0 + wn * 64;
    #pragma unroll
    for (int mt = 0; mt < 2; mt++) {
        #pragma unroll
        for (int j = 0; j < 8; j++) {
            const int r = wm * 32 + mt * 16 + lg;
            const int c = 8 * j + 2 * lt;
            const float* d = acc[mt][j];
            *reinterpret_cast<float2*>(outBase + (size_t)r * HID + c)       = make_float2(d[0], d[1]);
            *reinterpret_cast<float2*>(outBase + (size_t)(r + 8) * HID + c) = make_float2(d[2], d[3]);
        }
    }
}

// ===========================================================================
// Launch
// ===========================================================================
extern "C" void kernel_launch(void* const* d_in, const int* in_sizes, int n_in,
                              void* d_out, int out_size) {
    const float* X  = (const float*)d_in[0];
    const float* W1 = (const float*)d_in[2];
    const float* W2 = (const float*)d_in[3];
    float* out = (float*)d_out;

    __half* xh;  cudaGetSymbolAddress((void**)&xh,  g_Xh);
    __half* w1h; cudaGetSymbolAddress((void**)&w1h, g_W1h);

    cudaFuncSetAttribute(gemm1_kernel, cudaFuncAttributeMaxDynamicSharedMemorySize, SMEM_TOTAL);
    cudaFuncSetAttribute(gemm2_kernel, cudaFuncAttributeMaxDynamicSharedMemorySize, SMEM_TOTAL);

    const size_t nX4 = (size_t)TOK_E * NEXPERTS * HID / 4;
    const size_t nW4 = (size_t)NEXPERTS * HID * FFN2 / 4;
    cvt_fused_kernel<<<4096, 256>>>(X, W1, xh, w1h, nX4, nX4 + nW4);

    gemm1_kernel<<<dim3(23, TOK_E / 128, NEXPERTS), 256, SMEM_TOTAL>>>(W2);
    gemm2_kernel<<<dim3(HID / 128, TOK_E / 128, NEXPERTS), 256, SMEM_TOTAL>>>(out);
}